// round 12
// baseline (speedup 1.0000x reference)
#include <cuda_runtime.h>
#include <cuda_bf16.h>
#include <cuda_fp16.h>
#include <cstdint>

// EGCL_A2V — bf16 HMMA + ldmatrix, 192-row tiles (12 warps), dynamic tiles.
// gemm128 is software-pipelined: 8 in-flight B fragment buffers + double-
// buffered A, so every ldmatrix lands a full ks-iteration before its mma.
// x1 kept packed bf16 (xp[32]) to fit the register budget.

#define NF 128
#define H  128
#define C  3
#define B_MAX 256
#define THREADS 384
#define NW 12
#define TILE 192
#define NBLK 148
#define PAD 136
#define WSTRIDE (128*PAD)
#define BSTEP (16 * PAD * 2)

#define SMEM_SW 0
#define SMEM_SA 104448
#define SMEM_F  156672
#define SMEM_TOTAL 193280

// float-region layout
#define F_WR    0
#define F_BE2   128
#define F_BC1   256
#define F_WC2   384
#define F_SRAD  512          // [192][3]
#define F_SDIFF 1088         // [192][9]
#define F_SSM   2816         // [3][192]
#define F_SWP   3392         // [3][12][128]
#define F_SBID  8576         // int[192]

__device__ float g_V1[B_MAX * C * H];
__device__ float g_aggM[B_MAX * C * H];
__device__ float g_aggT[B_MAX * 9];
__device__ float g_cnt[B_MAX];
__device__ unsigned g_tile;
__device__ __align__(16) __nv_bfloat16 g_Wimg[3 * WSTRIDE];

// ---------------- helpers ----------------
__device__ __forceinline__ float silu_p(float x) { return x / (1.0f + __expf(-x)); }

__device__ __forceinline__ float2 silu2(float f0, float f1) {
    __half2 h  = __floats2half2_rn(f0, f1);
    __half2 hx = __hmul2(h, __float2half2_rn(0.5f));
    uint32_t hu = *reinterpret_cast<uint32_t*>(&hx);
    uint32_t tu;
    asm("tanh.approx.f16x2 %0, %1;" : "=r"(tu) : "r"(hu));
    __half2 t = *reinterpret_cast<__half2*>(&tu);
    __half2 s = __hfma2(hx, t, hx);
    return __half22float2(s);
}
__device__ __forceinline__ uint32_t pack_bf16(float lo, float hi) {
    uint32_t r;
    asm("cvt.rn.bf16x2.f32 %0, %1, %2;" : "=r"(r) : "f"(hi), "f"(lo));
    return r;
}
__device__ __forceinline__ float2 unpack_bf16(uint32_t u) {
    __nv_bfloat162 h = *reinterpret_cast<__nv_bfloat162*>(&u);
    return __bfloat1622float2(h);
}
__device__ __forceinline__ uint32_t smem_u32(const void* p) {
    uint32_t a;
    asm("{ .reg .u64 t; cvta.to.shared.u64 t, %1; cvt.u32.u64 %0, t; }" : "=r"(a) : "l"(p));
    return a;
}
__device__ __forceinline__ void ldsm_x4(uint32_t* r, uint32_t addr) {
    asm volatile("ldmatrix.sync.aligned.m8n8.x4.shared.b16 {%0,%1,%2,%3}, [%4];"
                 : "=r"(r[0]), "=r"(r[1]), "=r"(r[2]), "=r"(r[3]) : "r"(addr));
}
__device__ __forceinline__ void mma16816(float* d,
        uint32_t a0, uint32_t a1, uint32_t a2, uint32_t a3,
        uint32_t b0, uint32_t b1) {
    asm volatile(
        "mma.sync.aligned.m16n8k16.row.col.f32.bf16.bf16.f32 "
        "{%0,%1,%2,%3}, {%4,%5,%6,%7}, {%8,%9}, {%0,%1,%2,%3};"
        : "+f"(d[0]), "+f"(d[1]), "+f"(d[2]), "+f"(d[3])
        : "r"(a0), "r"(a1), "r"(a2), "r"(a3), "r"(b0), "r"(b1));
}

// Software-pipelined 128x128x128 GEMM: 8 in-flight B buffers + A double-buffer.
// Every ldmatrix result is consumed ~one full ks-iteration after issue.
__device__ __forceinline__ void gemm128(uint32_t aAddr, uint32_t bAddr, float* acc) {
    uint32_t A[4], An[4];
    uint32_t B0[4], B1[4], B2[4], B3[4], B4[4], B5[4], B6[4], B7[4];
    ldsm_x4(A,  aAddr);
    ldsm_x4(B0, bAddr);
    ldsm_x4(B1, bAddr + 1 * BSTEP);
    ldsm_x4(B2, bAddr + 2 * BSTEP);
    ldsm_x4(B3, bAddr + 3 * BSTEP);
    ldsm_x4(B4, bAddr + 4 * BSTEP);
    ldsm_x4(B5, bAddr + 5 * BSTEP);
    ldsm_x4(B6, bAddr + 6 * BSTEP);
    ldsm_x4(B7, bAddr + 7 * BSTEP);
#pragma unroll 2
    for (int ks = 0; ks < 8; ks++) {
        const int ksn32 = (ks < 7 ? ks + 1 : 7) * 32;
        ldsm_x4(An, aAddr + ksn32);
        mma16816(acc + 0,  A[0], A[1], A[2], A[3], B0[0], B0[1]);
        mma16816(acc + 4,  A[0], A[1], A[2], A[3], B0[2], B0[3]);
        ldsm_x4(B0, bAddr + 0 * BSTEP + ksn32);
        mma16816(acc + 8,  A[0], A[1], A[2], A[3], B1[0], B1[1]);
        mma16816(acc + 12, A[0], A[1], A[2], A[3], B1[2], B1[3]);
        ldsm_x4(B1, bAddr + 1 * BSTEP + ksn32);
        mma16816(acc + 16, A[0], A[1], A[2], A[3], B2[0], B2[1]);
        mma16816(acc + 20, A[0], A[1], A[2], A[3], B2[2], B2[3]);
        ldsm_x4(B2, bAddr + 2 * BSTEP + ksn32);
        mma16816(acc + 24, A[0], A[1], A[2], A[3], B3[0], B3[1]);
        mma16816(acc + 28, A[0], A[1], A[2], A[3], B3[2], B3[3]);
        ldsm_x4(B3, bAddr + 3 * BSTEP + ksn32);
        mma16816(acc + 32, A[0], A[1], A[2], A[3], B4[0], B4[1]);
        mma16816(acc + 36, A[0], A[1], A[2], A[3], B4[2], B4[3]);
        ldsm_x4(B4, bAddr + 4 * BSTEP + ksn32);
        mma16816(acc + 40, A[0], A[1], A[2], A[3], B5[0], B5[1]);
        mma16816(acc + 44, A[0], A[1], A[2], A[3], B5[2], B5[3]);
        ldsm_x4(B5, bAddr + 5 * BSTEP + ksn32);
        mma16816(acc + 48, A[0], A[1], A[2], A[3], B6[0], B6[1]);
        mma16816(acc + 52, A[0], A[1], A[2], A[3], B6[2], B6[3]);
        ldsm_x4(B6, bAddr + 6 * BSTEP + ksn32);
        mma16816(acc + 56, A[0], A[1], A[2], A[3], B7[0], B7[1]);
        mma16816(acc + 60, A[0], A[1], A[2], A[3], B7[2], B7[3]);
        ldsm_x4(B7, bAddr + 7 * BSTEP + ksn32);
        A[0] = An[0]; A[1] = An[1]; A[2] = An[2]; A[3] = An[3];
    }
}

// ---------------------------------------------------------------------------
__global__ void prep_img(const float* __restrict__ We1,
                         const float* __restrict__ We2,
                         const float* __restrict__ Wc1,
                         __nv_bfloat16* __restrict__ gW) {
    int w = blockIdx.x >> 7, k = blockIdx.x & 127, n = threadIdx.x;
    const float* W = (w == 0) ? We1 : (w == 1) ? We2 : Wc1;
    gW[w * WSTRIDE + n * PAD + k] = __float2bfloat16(W[k * H + n]);
}

// ---------------------------------------------------------------------------
__global__ void prep_V1(const float* __restrict__ vnf,
                        const float* __restrict__ We1,
                        const float* __restrict__ be1) {
    __shared__ float sv[NF];
    int h = threadIdx.x, bc = blockIdx.x;
    int b = bc / C, c = bc % C;
    sv[h] = vnf[(b * NF + h) * C + c];
    __syncthreads();
    const float* w = We1 + NF * H;
    float a0 = 0.f, a1 = 0.f, a2 = 0.f, a3 = 0.f;
    float a4 = 0.f, a5 = 0.f, a6 = 0.f, a7 = 0.f;
#pragma unroll 4
    for (int f = 0; f < NF; f += 8) {
        a0 = fmaf(sv[f],     __ldg(&w[(f)     * H + h]), a0);
        a1 = fmaf(sv[f + 1], __ldg(&w[(f + 1) * H + h]), a1);
        a2 = fmaf(sv[f + 2], __ldg(&w[(f + 2) * H + h]), a2);
        a3 = fmaf(sv[f + 3], __ldg(&w[(f + 3) * H + h]), a3);
        a4 = fmaf(sv[f + 4], __ldg(&w[(f + 4) * H + h]), a4);
        a5 = fmaf(sv[f + 5], __ldg(&w[(f + 5) * H + h]), a5);
        a6 = fmaf(sv[f + 6], __ldg(&w[(f + 6) * H + h]), a6);
        a7 = fmaf(sv[f + 7], __ldg(&w[(f + 7) * H + h]), a7);
    }
    g_V1[bc * H + h] = be1[h] + (((a0 + a1) + (a2 + a3)) + ((a4 + a5) + (a6 + a7)));
    g_aggM[bc * H + h] = 0.0f;
    if (bc == 0) {
        for (int i = h; i < B_MAX * 9; i += blockDim.x) g_aggT[i] = 0.0f;
        for (int i = h; i < B_MAX; i += blockDim.x) g_cnt[i] = 0.0f;
        if (h == 0) g_tile = 0u;
    }
}

// ---------------------------------------------------------------------------
__global__ void __launch_bounds__(THREADS, 1)
main_kernel(const float* __restrict__ node_feat,
            const float* __restrict__ coord,
            const float* __restrict__ vcoord,
            const int*   __restrict__ batch,
            const float* __restrict__ We1,
            const float* __restrict__ be2,
            const float* __restrict__ bc1,
            const float* __restrict__ Wc2,
            int N) {
    extern __shared__ __align__(16) char smem[];
    __nv_bfloat16* sW = (__nv_bfloat16*)(smem + SMEM_SW);
    __nv_bfloat16* sA = (__nv_bfloat16*)(smem + SMEM_SA);
    float* sf = (float*)(smem + SMEM_F);
    float* swr   = sf + F_WR;
    float* sbe2  = sf + F_BE2;
    float* sbc1  = sf + F_BC1;
    float* swc2  = sf + F_WC2;
    float* srad  = sf + F_SRAD;
    float* sdiff = sf + F_SDIFF;
    float* ssm   = sf + F_SSM;
    float* swp   = sf + F_SWP;
    int*   sbid  = (int*)(sf + F_SBID);
    __shared__ int s_tile;

    const int tid = threadIdx.x, lane = tid & 31, warp = tid >> 5;

    {   // weights -> smem
        const uint4* src = (const uint4*)g_Wimg;
        uint4* dst = (uint4*)sW;
        for (int i = tid; i < 3 * WSTRIDE * 2 / 16; i += THREADS) dst[i] = src[i];
    }
    if (tid < 128) {
        swr[tid]  = We1[256 * H + tid];
        sbe2[tid] = be2[tid];
        sbc1[tid] = bc1[tid];
        swc2[tid] = Wc2[tid];
    }
    __syncthreads();

    const uint32_t sA_u = smem_u32(sA);
    const uint32_t sW_u = smem_u32(sW);
    const uint32_t aAddr = sA_u +
        (((warp * 16 + (lane & 15)) * PAD + (lane >> 4) * 8) << 1);
    const uint32_t bRel =
        (((((lane >> 4) & 1) * 8 + (lane & 7)) * PAD + ((lane >> 3) & 1) * 8) << 1);
    const uint32_t bAddr0 = sW_u + bRel;
    const uint32_t bAddr1 = bAddr0 + WSTRIDE * 2;
    const uint32_t bAddr2 = bAddr1 + WSTRIDE * 2;
    const int r0 = warp * 16 + (lane >> 2), r1 = r0 + 8;

    const int ntiles = (N + TILE - 1) / TILE;
    for (;;) {
        if (tid == 0) s_tile = (int)atomicAdd(&g_tile, 1u);
        __syncthreads();                       // B1 (fences prev-tile agg too)
        const int t = s_tile;
        if (t >= ntiles) break;
        const int base = t * TILE;

        const bool tileFull = (base + TILE <= N);
        const int bFirst = __ldg(&batch[base]);
        const int bLast  = __ldg(&batch[min(base + TILE - 1, N - 1)]);
        const bool fast  = tileFull && (bFirst == bLast) && bFirst >= 0;
        const int b0t = bFirst < 0 ? 0 : bFirst;

        if (fast) {
            // ================= FAST PATH: warp-private, 2 CTA barriers ======
            {   // own-rows load
                int r = warp * 16 + (lane >> 1), cb = (lane & 1) * 64;
                int n = base + r;
                const float4* nf = (const float4*)(node_feat + (size_t)n * NF + cb);
                __nv_bfloat16* dst = sA + r * PAD + cb;
#pragma unroll
                for (int q = 0; q < 16; q++) {
                    float4 v = __ldg(&nf[q]);
                    *(uint32_t*)(dst + q * 4)     = pack_bf16(v.x, v.y);
                    *(uint32_t*)(dst + q * 4 + 2) = pack_bf16(v.z, v.w);
                }
                if (lane < 16) {   // geometry for own row warp*16+lane
                    int m = warp * 16 + lane, nn = base + m;
                    float cx = coord[nn * 3 + 0], cy = coord[nn * 3 + 1], cz = coord[nn * 3 + 2];
#pragma unroll
                    for (int cc = 0; cc < C; cc++) {
                        float dx = __ldg(&vcoord[(b0t * 3 + 0) * C + cc]) - cx;
                        float dy = __ldg(&vcoord[(b0t * 3 + 1) * C + cc]) - cy;
                        float dz = __ldg(&vcoord[(b0t * 3 + 2) * C + cc]) - cz;
                        sdiff[m * 9 + cc * 3 + 0] = dx;
                        sdiff[m * 9 + cc * 3 + 1] = dy;
                        sdiff[m * 9 + cc * 3 + 2] = dz;
                        srad[m * 3 + cc] = sqrtf(dx * dx + dy * dy + dz * dz);
                    }
                }
            }
            if (tid == 0) atomicAdd(&g_cnt[b0t], (float)TILE);
            __syncwarp();

            // GEMM1 -> xp (packed bf16, acc layout)
            uint32_t xp[32];
            {
                float x1[64];
#pragma unroll
                for (int i = 0; i < 64; i++) x1[i] = 0.f;
                gemm128(aAddr, bAddr0, x1);
#pragma unroll
                for (int nt = 0; nt < 16; nt++) {
                    xp[nt * 2 + 0] = pack_bf16(x1[nt * 4 + 0], x1[nt * 4 + 1]);
                    xp[nt * 2 + 1] = pack_bf16(x1[nt * 4 + 2], x1[nt * 4 + 3]);
                }
            }
            __syncwarp();

#pragma unroll 1
            for (int c = 0; c < C; c++) {
                // EpA
                float rad0 = srad[r0 * 3 + c], rad1 = srad[r1 * 3 + c];
                const float* v1p = g_V1 + (b0t * C + c) * H;
#pragma unroll
                for (int nt = 0; nt < 16; nt++) {
                    int c0 = nt * 8 + (lane & 3) * 2;
                    float2 xv0 = unpack_bf16(xp[nt * 2 + 0]);
                    float2 xv1 = unpack_bf16(xp[nt * 2 + 1]);
                    float2 vv = __ldg((const float2*)(v1p + c0));
                    float w0 = swr[c0], w1 = swr[c0 + 1];
                    float2 u0 = silu2(xv0.x + vv.x + rad0 * w0, xv0.y + vv.y + rad0 * w1);
                    float2 u1 = silu2(xv1.x + vv.x + rad1 * w0, xv1.y + vv.y + rad1 * w1);
                    *(uint32_t*)(sA + r0 * PAD + c0) = pack_bf16(u0.x, u0.y);
                    *(uint32_t*)(sA + r1 * PAD + c0) = pack_bf16(u1.x, u1.y);
                }
                __syncwarp();

                // GEMM2
                float acc[64];
#pragma unroll
                for (int i = 0; i < 64; i++) acc[i] = 0.f;
                gemm128(aAddr, bAddr1, acc);
                __syncwarp();

                // EpB: m2 -> sA; per-warp column sums -> swp[c][warp]
#pragma unroll
                for (int nt = 0; nt < 16; nt++) {
                    int c0 = nt * 8 + (lane & 3) * 2;
                    float2 u0 = silu2(acc[nt * 4 + 0] + sbe2[c0], acc[nt * 4 + 1] + sbe2[c0 + 1]);
                    float2 u1 = silu2(acc[nt * 4 + 2] + sbe2[c0], acc[nt * 4 + 3] + sbe2[c0 + 1]);
                    *(uint32_t*)(sA + r0 * PAD + c0) = pack_bf16(u0.x, u0.y);
                    *(uint32_t*)(sA + r1 * PAD + c0) = pack_bf16(u1.x, u1.y);
                    float v0 = u0.x + u1.x, v1 = u0.y + u1.y;
                    v0 += __shfl_xor_sync(0xffffffffu, v0, 4);
                    v0 += __shfl_xor_sync(0xffffffffu, v0, 8);
                    v0 += __shfl_xor_sync(0xffffffffu, v0, 16);
                    v1 += __shfl_xor_sync(0xffffffffu, v1, 4);
                    v1 += __shfl_xor_sync(0xffffffffu, v1, 8);
                    v1 += __shfl_xor_sync(0xffffffffu, v1, 16);
                    if (lane < 4) {
                        swp[(c * NW + warp) * 128 + c0]     = v0;
                        swp[(c * NW + warp) * 128 + c0 + 1] = v1;
                    }
                }
                __syncwarp();

                // GEMM3
#pragma unroll
                for (int i = 0; i < 64; i++) acc[i] = 0.f;
                gemm128(aAddr, bAddr2, acc);

                // EpC: row scalar s
                {
                    float s0 = 0.f, s1 = 0.f;
#pragma unroll
                    for (int nt = 0; nt < 16; nt++) {
                        int c0 = nt * 8 + (lane & 3) * 2;
                        float2 u0 = silu2(acc[nt * 4 + 0] + sbc1[c0], acc[nt * 4 + 1] + sbc1[c0 + 1]);
                        float2 u1 = silu2(acc[nt * 4 + 2] + sbc1[c0], acc[nt * 4 + 3] + sbc1[c0 + 1]);
                        s0 += u0.x * swc2[c0] + u0.y * swc2[c0 + 1];
                        s1 += u1.x * swc2[c0] + u1.y * swc2[c0 + 1];
                    }
                    s0 += __shfl_xor_sync(0xffffffffu, s0, 1);
                    s0 += __shfl_xor_sync(0xffffffffu, s0, 2);
                    s1 += __shfl_xor_sync(0xffffffffu, s1, 1);
                    s1 += __shfl_xor_sync(0xffffffffu, s1, 2);
                    if ((lane & 3) == 0) { ssm[c * TILE + r0] = s0; ssm[c * TILE + r1] = s1; }
                }
                __syncwarp();   // GEMM3 reads done before next EpA overwrites sA
            }

            __syncthreads();                   // B2: swp/ssm/sdiff visible

            // aggM: 128 cols x 3 channels
            if (tid < 128) {
#pragma unroll
                for (int c = 0; c < C; c++) {
                    float s = 0.f;
#pragma unroll
                    for (int w = 0; w < NW; w++) s += swp[(c * NW + w) * 128 + tid];
                    atomicAdd(&g_aggM[(b0t * C + c) * H + tid], s);
                }
            }
            // aggT: 9 (c,d) pairs by warps 0..8
            if (warp < 9) {
                int c = warp / 3, d = warp % 3;
                float v = 0.f;
#pragma unroll
                for (int q = 0; q < TILE / 32; q++) {
                    int r = lane + q * 32;
                    v += sdiff[r * 9 + c * 3 + d] * ssm[c * TILE + r];
                }
                v += __shfl_xor_sync(0xffffffffu, v, 16);
                v += __shfl_xor_sync(0xffffffffu, v, 8);
                v += __shfl_xor_sync(0xffffffffu, v, 4);
                v += __shfl_xor_sync(0xffffffffu, v, 2);
                v += __shfl_xor_sync(0xffffffffu, v, 1);
                if (lane == 0) atomicAdd(&g_aggT[b0t * 9 + d * 3 + c], v);
            }
            continue;   // loop-top B1 fences agg reads
        }

        // ================= SLOW PATH (segment boundary / tail) ==============
        if (tid < TILE) {
            int m = tid, n = base + m;
            bool valid = n < N;
            int nc = valid ? n : N - 1;
            int b = valid ? batch[n] : -1;
            sbid[m] = b;
            int bb = b < 0 ? 0 : b;
            float cx = coord[nc * 3 + 0], cy = coord[nc * 3 + 1], cz = coord[nc * 3 + 2];
#pragma unroll
            for (int cc = 0; cc < C; cc++) {
                float dx = __ldg(&vcoord[(bb * 3 + 0) * C + cc]) - cx;
                float dy = __ldg(&vcoord[(bb * 3 + 1) * C + cc]) - cy;
                float dz = __ldg(&vcoord[(bb * 3 + 2) * C + cc]) - cz;
                sdiff[m * 9 + cc * 3 + 0] = dx;
                sdiff[m * 9 + cc * 3 + 1] = dy;
                sdiff[m * 9 + cc * 3 + 2] = dz;
                srad[m * 3 + cc] = sqrtf(dx * dx + dy * dy + dz * dz);
            }
        }
        {
            int r = tid >> 1, cb = (tid & 1) * 64;
            int n = base + r;
            int nc = n < N ? n : N - 1;
            const float4* nf = (const float4*)(node_feat + (size_t)nc * NF + cb);
            __nv_bfloat16* dst = sA + r * PAD + cb;
#pragma unroll
            for (int q = 0; q < 16; q++) {
                float4 v = __ldg(&nf[q]);
                *(uint32_t*)(dst + q * 4)     = pack_bf16(v.x, v.y);
                *(uint32_t*)(dst + q * 4 + 2) = pack_bf16(v.z, v.w);
            }
        }
        __syncthreads();

        if (tid == 0) {
            int cb = sbid[0]; float cl = 0.f;
            for (int r = 0; r < TILE; r++) {
                int b2 = sbid[r];
                if (b2 != cb) { if (cb >= 0) atomicAdd(&g_cnt[cb], cl); cl = 0.f; cb = b2; }
                if (b2 >= 0) cl += 1.f;
            }
            if (cb >= 0) atomicAdd(&g_cnt[cb], cl);
        }

        int bb0 = sbid[r0]; bb0 = bb0 < 0 ? 0 : bb0;
        int bb1 = sbid[r1]; bb1 = bb1 < 0 ? 0 : bb1;

        uint32_t xp[32];
        {
            float x1[64];
#pragma unroll
            for (int i = 0; i < 64; i++) x1[i] = 0.f;
            gemm128(aAddr, bAddr0, x1);
#pragma unroll
            for (int nt = 0; nt < 16; nt++) {
                xp[nt * 2 + 0] = pack_bf16(x1[nt * 4 + 0], x1[nt * 4 + 1]);
                xp[nt * 2 + 1] = pack_bf16(x1[nt * 4 + 2], x1[nt * 4 + 3]);
            }
        }
        __syncthreads();

#pragma unroll 1
        for (int c = 0; c < C; c++) {
            float rad0 = srad[r0 * 3 + c], rad1 = srad[r1 * 3 + c];
            const float* v0p = g_V1 + (bb0 * C + c) * H;
            const float* v1p = g_V1 + (bb1 * C + c) * H;
#pragma unroll
            for (int nt = 0; nt < 16; nt++) {
                int c0 = nt * 8 + (lane & 3) * 2;
                float2 xv0 = unpack_bf16(xp[nt * 2 + 0]);
                float2 xv1 = unpack_bf16(xp[nt * 2 + 1]);
                float w0 = swr[c0], w1 = swr[c0 + 1];
                float2 u0 = silu2(xv0.x + __ldg(&v0p[c0])     + rad0 * w0,
                                  xv0.y + __ldg(&v0p[c0 + 1]) + rad0 * w1);
                float2 u1 = silu2(xv1.x + __ldg(&v1p[c0])     + rad1 * w0,
                                  xv1.y + __ldg(&v1p[c0 + 1]) + rad1 * w1);
                *(uint32_t*)(sA + r0 * PAD + c0) = pack_bf16(u0.x, u0.y);
                *(uint32_t*)(sA + r1 * PAD + c0) = pack_bf16(u1.x, u1.y);
            }
            __syncthreads();

            float acc[64];
#pragma unroll
            for (int i = 0; i < 64; i++) acc[i] = 0.f;
            gemm128(aAddr, bAddr1, acc);
            __syncthreads();

#pragma unroll
            for (int nt = 0; nt < 16; nt++) {
                int c0 = nt * 8 + (lane & 3) * 2;
                float2 u0 = silu2(acc[nt * 4 + 0] + sbe2[c0], acc[nt * 4 + 1] + sbe2[c0 + 1]);
                float2 u1 = silu2(acc[nt * 4 + 2] + sbe2[c0], acc[nt * 4 + 3] + sbe2[c0 + 1]);
                *(uint32_t*)(sA + r0 * PAD + c0) = pack_bf16(u0.x, u0.y);
                *(uint32_t*)(sA + r1 * PAD + c0) = pack_bf16(u1.x, u1.y);
            }
            __syncthreads();

#pragma unroll
            for (int i = 0; i < 64; i++) acc[i] = 0.f;
            gemm128(aAddr, bAddr2, acc);

            {
                float s0 = 0.f, s1 = 0.f;
#pragma unroll
                for (int nt = 0; nt < 16; nt++) {
                    int c0 = nt * 8 + (lane & 3) * 2;
                    float2 u0 = silu2(acc[nt * 4 + 0] + sbc1[c0], acc[nt * 4 + 1] + sbc1[c0 + 1]);
                    float2 u1 = silu2(acc[nt * 4 + 2] + sbc1[c0], acc[nt * 4 + 3] + sbc1[c0 + 1]);
                    s0 += u0.x * swc2[c0] + u0.y * swc2[c0 + 1];
                    s1 += u1.x * swc2[c0] + u1.y * swc2[c0 + 1];
                }
                s0 += __shfl_xor_sync(0xffffffffu, s0, 1);
                s0 += __shfl_xor_sync(0xffffffffu, s0, 2);
                s1 += __shfl_xor_sync(0xffffffffu, s1, 1);
                s1 += __shfl_xor_sync(0xffffffffu, s1, 2);
                if ((lane & 3) == 0) { ssm[r0] = s0; ssm[r1] = s1; }
            }
            __syncthreads();

            if (tid < 128) {
                int col = tid; float a = 0.f; int cb = sbid[0];
                for (int r = 0; r < TILE; r++) {
                    int b2 = sbid[r];
                    if (b2 != cb) {
                        if (cb >= 0) atomicAdd(&g_aggM[(cb * C + c) * H + col], a);
                        a = 0.f; cb = b2;
                    }
                    if (b2 >= 0) a += __bfloat162float(sA[r * PAD + col]);
                }
                if (cb >= 0) atomicAdd(&g_aggM[(cb * C + c) * H + col], a);
            }
            if (tid >= 128 && tid < 131) {
                int d = tid - 128; float a = 0.f; int cb = sbid[0];
                for (int r = 0; r < TILE; r++) {
                    int b2 = sbid[r];
                    if (b2 != cb) {
                        if (cb >= 0) atomicAdd(&g_aggT[cb * 9 + d * 3 + c], a);
                        a = 0.f; cb = b2;
                    }
                    if (b2 >= 0) a += sdiff[r * 9 + c * 3 + d] * ssm[r];
                }
                if (cb >= 0) atomicAdd(&g_aggT[cb * 9 + d * 3 + c], a);
            }
            __syncthreads();
        }
    }
}

// ---------------------------------------------------------------------------
// finalize: node MLP on B*C rows, split-K, 8-way MLP per thread
// ---------------------------------------------------------------------------
__global__ void final_kernel(const float* __restrict__ vnf,
                             const float* __restrict__ vcoord,
                             const float* __restrict__ Wn1, const float* __restrict__ bn1,
                             const float* __restrict__ Wn2, const float* __restrict__ bn2,
                             float* __restrict__ out, int B) {
    __shared__ float s_in[2 * H];
    __shared__ float s_h1[H];
    __shared__ float s_p[2 * H];
    int tid = threadIdx.x;
    int b = blockIdx.x / C, c = blockIdx.x % C;

    float cnt = fmaxf(g_cnt[b], 1.0f);
    if (tid < 128) {
        s_in[tid]       = vnf[(b * NF + tid) * C + c];
        s_in[128 + tid] = g_aggM[(b * C + c) * H + tid] / cnt;
    }
    __syncthreads();
    {
        int col = tid & 127, half = tid >> 7;
        const float* w  = Wn1 + half * 128 * H;
        const float* xi = s_in + half * 128;
        float a0 = 0.f, a1 = 0.f, a2 = 0.f, a3 = 0.f;
        float a4 = 0.f, a5 = 0.f, a6 = 0.f, a7 = 0.f;
#pragma unroll 16
        for (int k = 0; k < 128; k += 8) {
            a0 = fmaf(xi[k],     __ldg(&w[(k)     * H + col]), a0);
            a1 = fmaf(xi[k + 1], __ldg(&w[(k + 1) * H + col]), a1);
            a2 = fmaf(xi[k + 2], __ldg(&w[(k + 2) * H + col]), a2);
            a3 = fmaf(xi[k + 3], __ldg(&w[(k + 3) * H + col]), a3);
            a4 = fmaf(xi[k + 4], __ldg(&w[(k + 4) * H + col]), a4);
            a5 = fmaf(xi[k + 5], __ldg(&w[(k + 5) * H + col]), a5);
            a6 = fmaf(xi[k + 6], __ldg(&w[(k + 6) * H + col]), a6);
            a7 = fmaf(xi[k + 7], __ldg(&w[(k + 7) * H + col]), a7);
        }
        s_p[half * 128 + col] = (((a0 + a1) + (a2 + a3)) + ((a4 + a5) + (a6 + a7)));
    }
    __syncthreads();
    if (tid < 128) s_h1[tid] = silu_p(bn1[tid] + s_p[tid] + s_p[128 + tid]);
    __syncthreads();
    {
        int col = tid & 127, half = tid >> 7;
        const float* hi = s_h1 + half * 64;
        const float* w  = Wn2 + half * 64 * H;
        float a0 = 0.f, a1 = 0.f, a2 = 0.f, a3 = 0.f;
        float a4 = 0.f, a5 = 0.f, a6 = 0.f, a7 = 0.f;
#pragma unroll 8
        for (int k = 0; k < 64; k += 8) {
            a0 = fmaf(hi[k],     __ldg(&w[(k)     * H + col]), a0);
            a1 = fmaf(hi[k + 1], __ldg(&w[(k + 1) * H + col]), a1);
            a2 = fmaf(hi[k + 2], __ldg(&w[(k + 2) * H + col]), a2);
            a3 = fmaf(hi[k + 3], __ldg(&w[(k + 3) * H + col]), a3);
            a4 = fmaf(hi[k + 4], __ldg(&w[(k + 4) * H + col]), a4);
            a5 = fmaf(hi[k + 5], __ldg(&w[(k + 5) * H + col]), a5);
            a6 = fmaf(hi[k + 6], __ldg(&w[(k + 6) * H + col]), a6);
            a7 = fmaf(hi[k + 7], __ldg(&w[(k + 7) * H + col]), a7);
        }
        s_p[half * 128 + col] = (((a0 + a1) + (a2 + a3)) + ((a4 + a5) + (a6 + a7)));
    }
    __syncthreads();
    if (tid < 128)
        out[(b * NF + tid) * C + c] =
            vnf[(b * NF + tid) * C + c] + bn2[tid] + s_p[tid] + s_p[128 + tid];

    if (c == 0 && tid >= 128 && tid < 137) {
        int t = tid - 128;
        int d = t / 3, cc = t % 3;
        int idx = (b * 3 + d) * C + cc;
        out[B * NF * C + idx] = vcoord[idx] + g_aggT[idx] / cnt;
    }
}

// ---------------------------------------------------------------------------
extern "C" void kernel_launch(void* const* d_in, const int* in_sizes, int n_in,
                              void* d_out, int out_size) {
    const float* node_feat = (const float*)d_in[0];
    const float* coord     = (const float*)d_in[1];
    const float* vnf       = (const float*)d_in[2];
    const float* vcoord    = (const float*)d_in[3];
    const int*   batch     = (const int*)  d_in[4];
    const float* We1 = (const float*)d_in[5];
    const float* be1 = (const float*)d_in[6];
    const float* We2 = (const float*)d_in[7];
    const float* be2 = (const float*)d_in[8];
    const float* Wc1 = (const float*)d_in[9];
    const float* bc1 = (const float*)d_in[10];
    const float* Wc2 = (const float*)d_in[11];
    const float* Wn1 = (const float*)d_in[12];
    const float* bn1 = (const float*)d_in[13];
    const float* Wn2 = (const float*)d_in[14];
    const float* bn2 = (const float*)d_in[15];

    int N = in_sizes[0] / NF;
    int B = in_sizes[2] / (NF * C);

    cudaFuncSetAttribute(main_kernel,
                         cudaFuncAttributeMaxDynamicSharedMemorySize, SMEM_TOTAL);

    __nv_bfloat16* gW = nullptr;
    cudaGetSymbolAddress((void**)&gW, g_Wimg);

    prep_img<<<3 * 128, 128>>>(We1, We2, Wc1, gW);
    prep_V1<<<B * C, 128>>>(vnf, We1, be1);
    main_kernel<<<NBLK, THREADS, SMEM_TOTAL>>>(node_feat, coord, vcoord, batch,
                                               We1, be2, bc1, Wc2, N);
    final_kernel<<<B * C, 256>>>(vnf, vcoord, Wn1, bn1, Wn2, bn2,
                                 (float*)d_out, B);
}

// round 13
// speedup vs baseline: 1.0378x; 1.0378x over previous
#include <cuda_runtime.h>
#include <cuda_bf16.h>
#include <cuda_fp16.h>
#include <cstdint>

// EGCL_A2V — single fused persistent kernel.
// Phase 0: weight images -> smem, V1 precompute, accumulator zeroing.
// Phase 1: R11-proven HMMA main loop (192-row tiles, 12 warps, dynamic tiles,
//          2-barrier fast path for single-segment tiles).
// Phase 2: node MLP finalize + both outputs.
// Grid barriers: monotonic-ticket (replay-safe), 148 co-resident CTAs.

#define NF 128
#define H  128
#define C  3
#define B_MAX 256
#define THREADS 384
#define NW 12
#define TILE 192
#define NBLK 148
#define PAD 136
#define WSTRIDE (128*PAD)

#define SMEM_SW 0
#define SMEM_SA 104448
#define SMEM_F  156672
#define SMEM_TOTAL 193280

// float-region layout
#define F_WR    0
#define F_BE2   128
#define F_BC1   256
#define F_WC2   384
#define F_SRAD  512          // [192][3]
#define F_SDIFF 1088         // [192][9]
#define F_SSM   2816         // [3][192]
#define F_SWP   3392         // [3][12][128]  (phase-2 scratch too)
#define F_SBID  8576         // int[192]

__device__ float g_V1[B_MAX * C * H];
__device__ float g_aggM[B_MAX * C * H];
__device__ float g_aggT[B_MAX * 9];
__device__ float g_cnt[B_MAX];
__device__ unsigned g_tile;
__device__ unsigned g_bar0 = 0, g_bar1 = 0;

// ---------------- helpers ----------------
__device__ __forceinline__ float silu_p(float x) { return x / (1.0f + __expf(-x)); }

__device__ __forceinline__ float2 silu2(float f0, float f1) {
    __half2 h  = __floats2half2_rn(f0, f1);
    __half2 hx = __hmul2(h, __float2half2_rn(0.5f));
    uint32_t hu = *reinterpret_cast<uint32_t*>(&hx);
    uint32_t tu;
    asm("tanh.approx.f16x2 %0, %1;" : "=r"(tu) : "r"(hu));
    __half2 t = *reinterpret_cast<__half2*>(&tu);
    __half2 s = __hfma2(hx, t, hx);
    return __half22float2(s);
}
__device__ __forceinline__ uint32_t pack_bf16(float lo, float hi) {
    uint32_t r;
    asm("cvt.rn.bf16x2.f32 %0, %1, %2;" : "=r"(r) : "f"(hi), "f"(lo));
    return r;
}
__device__ __forceinline__ uint32_t smem_u32(const void* p) {
    uint32_t a;
    asm("{ .reg .u64 t; cvta.to.shared.u64 t, %1; cvt.u32.u64 %0, t; }" : "=r"(a) : "l"(p));
    return a;
}
__device__ __forceinline__ void ldsm_x4(uint32_t* r, uint32_t addr) {
    asm volatile("ldmatrix.sync.aligned.m8n8.x4.shared.b16 {%0,%1,%2,%3}, [%4];"
                 : "=r"(r[0]), "=r"(r[1]), "=r"(r[2]), "=r"(r[3]) : "r"(addr));
}
__device__ __forceinline__ void mma16816(float* d,
        uint32_t a0, uint32_t a1, uint32_t a2, uint32_t a3,
        uint32_t b0, uint32_t b1) {
    asm volatile(
        "mma.sync.aligned.m16n8k16.row.col.f32.bf16.bf16.f32 "
        "{%0,%1,%2,%3}, {%4,%5,%6,%7}, {%8,%9}, {%0,%1,%2,%3};"
        : "+f"(d[0]), "+f"(d[1]), "+f"(d[2]), "+f"(d[3])
        : "r"(a0), "r"(a1), "r"(a2), "r"(a3), "r"(b0), "r"(b1));
}
__device__ __forceinline__ void gemm128(uint32_t aAddr, uint32_t bAddr, float* acc) {
#pragma unroll 2
    for (int ks = 0; ks < 8; ks++) {
        uint32_t A[4];
        ldsm_x4(A, aAddr + ks * 32);
#pragma unroll
        for (int ntp = 0; ntp < 8; ntp++) {
            uint32_t Bf[4];
            ldsm_x4(Bf, bAddr + ntp * (16 * PAD * 2) + ks * 32);
            mma16816(acc + ntp * 8,     A[0], A[1], A[2], A[3], Bf[0], Bf[1]);
            mma16816(acc + ntp * 8 + 4, A[0], A[1], A[2], A[3], Bf[2], Bf[3]);
        }
    }
}

// monotonic-ticket grid barrier (all NBLK CTAs resident; replay-safe)
__device__ __forceinline__ void grid_barrier(unsigned* ctr) {
    __syncthreads();
    if (threadIdx.x == 0) {
        unsigned my;
        asm volatile("atom.add.release.gpu.u32 %0, [%1], 1;"
                     : "=r"(my) : "l"(ctr) : "memory");
        unsigned target = (my / NBLK + 1u) * NBLK;
        unsigned v;
        do {
            asm volatile("ld.acquire.gpu.u32 %0, [%1];" : "=r"(v) : "l"(ctr) : "memory");
        } while ((int)(v - target) < 0);
    }
    __syncthreads();
}

// ---------------------------------------------------------------------------
__global__ void __launch_bounds__(THREADS, 1)
egcl_kernel(const float* __restrict__ node_feat,
            const float* __restrict__ coord,
            const float* __restrict__ vnf,
            const float* __restrict__ vcoord,
            const int*   __restrict__ batch,
            const float* __restrict__ We1, const float* __restrict__ be1,
            const float* __restrict__ We2, const float* __restrict__ be2,
            const float* __restrict__ Wc1, const float* __restrict__ bc1,
            const float* __restrict__ Wc2,
            const float* __restrict__ Wn1, const float* __restrict__ bn1,
            const float* __restrict__ Wn2, const float* __restrict__ bn2,
            float* __restrict__ out, int N, int B) {
    extern __shared__ __align__(16) char smem[];
    __nv_bfloat16* sW = (__nv_bfloat16*)(smem + SMEM_SW);
    __nv_bfloat16* sA = (__nv_bfloat16*)(smem + SMEM_SA);
    float* sf = (float*)(smem + SMEM_F);
    float* swr   = sf + F_WR;
    float* sbe2  = sf + F_BE2;
    float* sbc1  = sf + F_BC1;
    float* swc2  = sf + F_WC2;
    float* srad  = sf + F_SRAD;
    float* sdiff = sf + F_SDIFF;
    float* ssm   = sf + F_SSM;
    float* swp   = sf + F_SWP;
    int*   sbid  = (int*)(sf + F_SBID);
    __shared__ int s_tile;

    const int tid = threadIdx.x, lane = tid & 31, warp = tid >> 5;
    const int bid = blockIdx.x;

    // ================= phase 0: prep =================
    // weight images (bf16, transposed, PAD-strided) built directly in smem
    for (int i = tid; i < 3 * 128 * 128; i += THREADS) {
        int w = i >> 14, rem = i & 16383, k = rem >> 7, n = rem & 127;
        const float* W = (w == 0) ? We1 : (w == 1) ? We2 : Wc1;
        sW[w * WSTRIDE + n * PAD + k] = __float2bfloat16(__ldg(&W[k * H + n]));
    }
    if (tid < 128) {
        swr[tid]  = We1[256 * H + tid];
        sbe2[tid] = be2[tid];
        sbc1[tid] = bc1[tid];
        swc2[tid] = Wc2[tid];
    }
    // zero global accumulators (grid-strided)
    for (int i = bid * THREADS + tid; i < B * C * H; i += NBLK * THREADS) g_aggM[i] = 0.f;
    for (int i = bid * THREADS + tid; i < B_MAX * 9; i += NBLK * THREADS) g_aggT[i] = 0.f;
    for (int i = bid * THREADS + tid; i < B_MAX;     i += NBLK * THREADS) g_cnt[i]  = 0.f;
    if (bid == 0 && tid == 0) g_tile = 0u;   // ordered by grid_barrier release/acquire
    // V1[b,c,h] = be1[h] + vnf[b,:,c] @ We1[128:256] (8-way MLP)
    for (int r = bid; r < B * C; r += NBLK) {
        if (tid < 128) {
            int b = r / C, c = r % C, h = tid;
            const float* w = We1 + NF * H;
            float a0 = 0.f, a1 = 0.f, a2 = 0.f, a3 = 0.f;
            float a4 = 0.f, a5 = 0.f, a6 = 0.f, a7 = 0.f;
#pragma unroll 4
            for (int f = 0; f < NF; f += 8) {
                a0 = fmaf(__ldg(&vnf[(b * NF + f)     * C + c]), __ldg(&w[(f)     * H + h]), a0);
                a1 = fmaf(__ldg(&vnf[(b * NF + f + 1) * C + c]), __ldg(&w[(f + 1) * H + h]), a1);
                a2 = fmaf(__ldg(&vnf[(b * NF + f + 2) * C + c]), __ldg(&w[(f + 2) * H + h]), a2);
                a3 = fmaf(__ldg(&vnf[(b * NF + f + 3) * C + c]), __ldg(&w[(f + 3) * H + h]), a3);
                a4 = fmaf(__ldg(&vnf[(b * NF + f + 4) * C + c]), __ldg(&w[(f + 4) * H + h]), a4);
                a5 = fmaf(__ldg(&vnf[(b * NF + f + 5) * C + c]), __ldg(&w[(f + 5) * H + h]), a5);
                a6 = fmaf(__ldg(&vnf[(b * NF + f + 6) * C + c]), __ldg(&w[(f + 6) * H + h]), a6);
                a7 = fmaf(__ldg(&vnf[(b * NF + f + 7) * C + c]), __ldg(&w[(f + 7) * H + h]), a7);
            }
            g_V1[r * H + h] = be1[h] + (((a0 + a1) + (a2 + a3)) + ((a4 + a5) + (a6 + a7)));
        }
    }
    grid_barrier(&g_bar0);

    // ================= phase 1: main loop (R11-proven body) =================
    const uint32_t sA_u = smem_u32(sA);
    const uint32_t sW_u = smem_u32(sW);
    const uint32_t aAddr = sA_u +
        (((warp * 16 + (lane & 15)) * PAD + (lane >> 4) * 8) << 1);
    const uint32_t bRel =
        (((((lane >> 4) & 1) * 8 + (lane & 7)) * PAD + ((lane >> 3) & 1) * 8) << 1);
    const uint32_t bAddr0 = sW_u + bRel;
    const uint32_t bAddr1 = bAddr0 + WSTRIDE * 2;
    const uint32_t bAddr2 = bAddr1 + WSTRIDE * 2;
    const int r0 = warp * 16 + (lane >> 2), r1 = r0 + 8;

    const int ntiles = (N + TILE - 1) / TILE;
    for (;;) {
        if (tid == 0) s_tile = (int)atomicAdd(&g_tile, 1u);
        __syncthreads();                       // B1 (fences prev-tile agg too)
        const int t = s_tile;
        if (t >= ntiles) break;
        const int base = t * TILE;

        const bool tileFull = (base + TILE <= N);
        const int bFirst = __ldg(&batch[base]);
        const int bLast  = __ldg(&batch[min(base + TILE - 1, N - 1)]);
        const bool fast  = tileFull && (bFirst == bLast) && bFirst >= 0;
        const int b0t = bFirst < 0 ? 0 : bFirst;

        if (fast) {
            // ================= FAST PATH: warp-private, 2 CTA barriers ======
            {   // own-rows load
                int r = warp * 16 + (lane >> 1), cb = (lane & 1) * 64;
                int n = base + r;
                const float4* nf = (const float4*)(node_feat + (size_t)n * NF + cb);
                __nv_bfloat16* dst = sA + r * PAD + cb;
#pragma unroll
                for (int q = 0; q < 16; q++) {
                    float4 v = __ldg(&nf[q]);
                    *(uint32_t*)(dst + q * 4)     = pack_bf16(v.x, v.y);
                    *(uint32_t*)(dst + q * 4 + 2) = pack_bf16(v.z, v.w);
                }
                if (lane < 16) {   // geometry for own row warp*16+lane
                    int m = warp * 16 + lane, nn = base + m;
                    float cx = coord[nn * 3 + 0], cy = coord[nn * 3 + 1], cz = coord[nn * 3 + 2];
#pragma unroll
                    for (int cc = 0; cc < C; cc++) {
                        float dx = __ldg(&vcoord[(b0t * 3 + 0) * C + cc]) - cx;
                        float dy = __ldg(&vcoord[(b0t * 3 + 1) * C + cc]) - cy;
                        float dz = __ldg(&vcoord[(b0t * 3 + 2) * C + cc]) - cz;
                        sdiff[m * 9 + cc * 3 + 0] = dx;
                        sdiff[m * 9 + cc * 3 + 1] = dy;
                        sdiff[m * 9 + cc * 3 + 2] = dz;
                        srad[m * 3 + cc] = sqrtf(dx * dx + dy * dy + dz * dz);
                    }
                }
            }
            if (tid == 0) atomicAdd(&g_cnt[b0t], (float)TILE);
            __syncwarp();

            // GEMM1
            float x1[64];
#pragma unroll
            for (int i = 0; i < 64; i++) x1[i] = 0.f;
            gemm128(aAddr, bAddr0, x1);
            __syncwarp();

#pragma unroll 1
            for (int c = 0; c < C; c++) {
                // EpA
                float rad0 = srad[r0 * 3 + c], rad1 = srad[r1 * 3 + c];
                const float* v1p = g_V1 + (b0t * C + c) * H;
#pragma unroll
                for (int nt = 0; nt < 16; nt++) {
                    int c0 = nt * 8 + (lane & 3) * 2;
                    float2 vv = __ldg((const float2*)(v1p + c0));
                    float w0 = swr[c0], w1 = swr[c0 + 1];
                    float2 u0 = silu2(x1[nt * 4 + 0] + vv.x + rad0 * w0,
                                      x1[nt * 4 + 1] + vv.y + rad0 * w1);
                    float2 u1 = silu2(x1[nt * 4 + 2] + vv.x + rad1 * w0,
                                      x1[nt * 4 + 3] + vv.y + rad1 * w1);
                    *(uint32_t*)(sA + r0 * PAD + c0) = pack_bf16(u0.x, u0.y);
                    *(uint32_t*)(sA + r1 * PAD + c0) = pack_bf16(u1.x, u1.y);
                }
                __syncwarp();

                // GEMM2
                float acc[64];
#pragma unroll
                for (int i = 0; i < 64; i++) acc[i] = 0.f;
                gemm128(aAddr, bAddr1, acc);
                __syncwarp();

                // EpB: m2 -> sA; per-warp column sums -> swp[c][warp]
#pragma unroll
                for (int nt = 0; nt < 16; nt++) {
                    int c0 = nt * 8 + (lane & 3) * 2;
                    float2 u0 = silu2(acc[nt * 4 + 0] + sbe2[c0], acc[nt * 4 + 1] + sbe2[c0 + 1]);
                    float2 u1 = silu2(acc[nt * 4 + 2] + sbe2[c0], acc[nt * 4 + 3] + sbe2[c0 + 1]);
                    *(uint32_t*)(sA + r0 * PAD + c0) = pack_bf16(u0.x, u0.y);
                    *(uint32_t*)(sA + r1 * PAD + c0) = pack_bf16(u1.x, u1.y);
                    float v0 = u0.x + u1.x, v1 = u0.y + u1.y;
                    v0 += __shfl_xor_sync(0xffffffffu, v0, 4);
                    v0 += __shfl_xor_sync(0xffffffffu, v0, 8);
                    v0 += __shfl_xor_sync(0xffffffffu, v0, 16);
                    v1 += __shfl_xor_sync(0xffffffffu, v1, 4);
                    v1 += __shfl_xor_sync(0xffffffffu, v1, 8);
                    v1 += __shfl_xor_sync(0xffffffffu, v1, 16);
                    if (lane < 4) {
                        swp[(c * NW + warp) * 128 + c0]     = v0;
                        swp[(c * NW + warp) * 128 + c0 + 1] = v1;
                    }
                }
                __syncwarp();

                // GEMM3
#pragma unroll
                for (int i = 0; i < 64; i++) acc[i] = 0.f;
                gemm128(aAddr, bAddr2, acc);

                // EpC: row scalar s
                {
                    float s0 = 0.f, s1 = 0.f;
#pragma unroll
                    for (int nt = 0; nt < 16; nt++) {
                        int c0 = nt * 8 + (lane & 3) * 2;
                        float2 u0 = silu2(acc[nt * 4 + 0] + sbc1[c0], acc[nt * 4 + 1] + sbc1[c0 + 1]);
                        float2 u1 = silu2(acc[nt * 4 + 2] + sbc1[c0], acc[nt * 4 + 3] + sbc1[c0 + 1]);
                        s0 += u0.x * swc2[c0] + u0.y * swc2[c0 + 1];
                        s1 += u1.x * swc2[c0] + u1.y * swc2[c0 + 1];
                    }
                    s0 += __shfl_xor_sync(0xffffffffu, s0, 1);
                    s0 += __shfl_xor_sync(0xffffffffu, s0, 2);
                    s1 += __shfl_xor_sync(0xffffffffu, s1, 1);
                    s1 += __shfl_xor_sync(0xffffffffu, s1, 2);
                    if ((lane & 3) == 0) { ssm[c * TILE + r0] = s0; ssm[c * TILE + r1] = s1; }
                }
                __syncwarp();   // GEMM3 reads done before next EpA overwrites sA
            }

            __syncthreads();                   // B2: swp/ssm/sdiff visible

            // aggM: 128 cols x 3 channels
            if (tid < 128) {
#pragma unroll
                for (int c = 0; c < C; c++) {
                    float s = 0.f;
#pragma unroll
                    for (int w = 0; w < NW; w++) s += swp[(c * NW + w) * 128 + tid];
                    atomicAdd(&g_aggM[(b0t * C + c) * H + tid], s);
                }
            }
            // aggT: 9 (c,d) pairs by warps 0..8
            if (warp < 9) {
                int c = warp / 3, d = warp % 3;
                float v = 0.f;
#pragma unroll
                for (int q = 0; q < TILE / 32; q++) {
                    int r = lane + q * 32;
                    v += sdiff[r * 9 + c * 3 + d] * ssm[c * TILE + r];
                }
                v += __shfl_xor_sync(0xffffffffu, v, 16);
                v += __shfl_xor_sync(0xffffffffu, v, 8);
                v += __shfl_xor_sync(0xffffffffu, v, 4);
                v += __shfl_xor_sync(0xffffffffu, v, 2);
                v += __shfl_xor_sync(0xffffffffu, v, 1);
                if (lane == 0) atomicAdd(&g_aggT[b0t * 9 + d * 3 + c], v);
            }
            continue;   // loop-top B1 fences agg reads
        }

        // ================= SLOW PATH (segment boundary / tail) ==============
        if (tid < TILE) {
            int m = tid, n = base + m;
            bool valid = n < N;
            int nc = valid ? n : N - 1;
            int b = valid ? batch[n] : -1;
            sbid[m] = b;
            int bb = b < 0 ? 0 : b;
            float cx = coord[nc * 3 + 0], cy = coord[nc * 3 + 1], cz = coord[nc * 3 + 2];
#pragma unroll
            for (int cc = 0; cc < C; cc++) {
                float dx = __ldg(&vcoord[(bb * 3 + 0) * C + cc]) - cx;
                float dy = __ldg(&vcoord[(bb * 3 + 1) * C + cc]) - cy;
                float dz = __ldg(&vcoord[(bb * 3 + 2) * C + cc]) - cz;
                sdiff[m * 9 + cc * 3 + 0] = dx;
                sdiff[m * 9 + cc * 3 + 1] = dy;
                sdiff[m * 9 + cc * 3 + 2] = dz;
                srad[m * 3 + cc] = sqrtf(dx * dx + dy * dy + dz * dz);
            }
        }
        {
            int r = tid >> 1, cb = (tid & 1) * 64;
            int n = base + r;
            int nc = n < N ? n : N - 1;
            const float4* nf = (const float4*)(node_feat + (size_t)nc * NF + cb);
            __nv_bfloat16* dst = sA + r * PAD + cb;
#pragma unroll
            for (int q = 0; q < 16; q++) {
                float4 v = __ldg(&nf[q]);
                *(uint32_t*)(dst + q * 4)     = pack_bf16(v.x, v.y);
                *(uint32_t*)(dst + q * 4 + 2) = pack_bf16(v.z, v.w);
            }
        }
        __syncthreads();

        if (tid == 0) {
            int cb = sbid[0]; float cl = 0.f;
            for (int r = 0; r < TILE; r++) {
                int b2 = sbid[r];
                if (b2 != cb) { if (cb >= 0) atomicAdd(&g_cnt[cb], cl); cl = 0.f; cb = b2; }
                if (b2 >= 0) cl += 1.f;
            }
            if (cb >= 0) atomicAdd(&g_cnt[cb], cl);
        }

        int bb0 = sbid[r0]; bb0 = bb0 < 0 ? 0 : bb0;
        int bb1 = sbid[r1]; bb1 = bb1 < 0 ? 0 : bb1;

        float x1[64];
#pragma unroll
        for (int i = 0; i < 64; i++) x1[i] = 0.f;
        gemm128(aAddr, bAddr0, x1);
        __syncthreads();

#pragma unroll 1
        for (int c = 0; c < C; c++) {
            float rad0 = srad[r0 * 3 + c], rad1 = srad[r1 * 3 + c];
            const float* v0p = g_V1 + (bb0 * C + c) * H;
            const float* v1p = g_V1 + (bb1 * C + c) * H;
#pragma unroll
            for (int nt = 0; nt < 16; nt++) {
                int c0 = nt * 8 + (lane & 3) * 2;
                float w0 = swr[c0], w1 = swr[c0 + 1];
                float2 u0 = silu2(x1[nt * 4 + 0] + __ldg(&v0p[c0])     + rad0 * w0,
                                  x1[nt * 4 + 1] + __ldg(&v0p[c0 + 1]) + rad0 * w1);
                float2 u1 = silu2(x1[nt * 4 + 2] + __ldg(&v1p[c0])     + rad1 * w0,
                                  x1[nt * 4 + 3] + __ldg(&v1p[c0 + 1]) + rad1 * w1);
                *(uint32_t*)(sA + r0 * PAD + c0) = pack_bf16(u0.x, u0.y);
                *(uint32_t*)(sA + r1 * PAD + c0) = pack_bf16(u1.x, u1.y);
            }
            __syncthreads();

            float acc[64];
#pragma unroll
            for (int i = 0; i < 64; i++) acc[i] = 0.f;
            gemm128(aAddr, bAddr1, acc);
            __syncthreads();

#pragma unroll
            for (int nt = 0; nt < 16; nt++) {
                int c0 = nt * 8 + (lane & 3) * 2;
                float2 u0 = silu2(acc[nt * 4 + 0] + sbe2[c0], acc[nt * 4 + 1] + sbe2[c0 + 1]);
                float2 u1 = silu2(acc[nt * 4 + 2] + sbe2[c0], acc[nt * 4 + 3] + sbe2[c0 + 1]);
                *(uint32_t*)(sA + r0 * PAD + c0) = pack_bf16(u0.x, u0.y);
                *(uint32_t*)(sA + r1 * PAD + c0) = pack_bf16(u1.x, u1.y);
            }
            __syncthreads();

#pragma unroll
            for (int i = 0; i < 64; i++) acc[i] = 0.f;
            gemm128(aAddr, bAddr2, acc);

            {
                float s0 = 0.f, s1 = 0.f;
#pragma unroll
                for (int nt = 0; nt < 16; nt++) {
                    int c0 = nt * 8 + (lane & 3) * 2;
                    float2 u0 = silu2(acc[nt * 4 + 0] + sbc1[c0], acc[nt * 4 + 1] + sbc1[c0 + 1]);
                    float2 u1 = silu2(acc[nt * 4 + 2] + sbc1[c0], acc[nt * 4 + 3] + sbc1[c0 + 1]);
                    s0 += u0.x * swc2[c0] + u0.y * swc2[c0 + 1];
                    s1 += u1.x * swc2[c0] + u1.y * swc2[c0 + 1];
                }
                s0 += __shfl_xor_sync(0xffffffffu, s0, 1);
                s0 += __shfl_xor_sync(0xffffffffu, s0, 2);
                s1 += __shfl_xor_sync(0xffffffffu, s1, 1);
                s1 += __shfl_xor_sync(0xffffffffu, s1, 2);
                if ((lane & 3) == 0) { ssm[r0] = s0; ssm[r1] = s1; }
            }
            __syncthreads();

            if (tid < 128) {
                int col = tid; float a = 0.f; int cb = sbid[0];
                for (int r = 0; r < TILE; r++) {
                    int b2 = sbid[r];
                    if (b2 != cb) {
                        if (cb >= 0) atomicAdd(&g_aggM[(cb * C + c) * H + col], a);
                        a = 0.f; cb = b2;
                    }
                    if (b2 >= 0) a += __bfloat162float(sA[r * PAD + col]);
                }
                if (cb >= 0) atomicAdd(&g_aggM[(cb * C + c) * H + col], a);
            }
            if (tid >= 128 && tid < 131) {
                int d = tid - 128; float a = 0.f; int cb = sbid[0];
                for (int r = 0; r < TILE; r++) {
                    int b2 = sbid[r];
                    if (b2 != cb) {
                        if (cb >= 0) atomicAdd(&g_aggT[cb * 9 + d * 3 + c], a);
                        a = 0.f; cb = b2;
                    }
                    if (b2 >= 0) a += sdiff[r * 9 + c * 3 + d] * ssm[r];
                }
                if (cb >= 0) atomicAdd(&g_aggT[cb * 9 + d * 3 + c], a);
            }
            __syncthreads();
        }
    }
    grid_barrier(&g_bar1);

    // ================= phase 2: finalize =================
    float* s_in = swp;          // [256]
    float* s_h1 = swp + 256;    // [128]
    float* s_p  = swp + 384;    // [256]
    for (int r = bid; r < B * C; r += NBLK) {
        int b = r / C, c = r % C;
        float cnt = fmaxf(g_cnt[b], 1.0f);
        if (tid < 128) {
            s_in[tid]       = vnf[(b * NF + tid) * C + c];
            s_in[128 + tid] = g_aggM[r * H + tid] / cnt;
        }
        __syncthreads();
        if (tid < 256) {
            int col = tid & 127, half = tid >> 7;
            const float* w  = Wn1 + half * 128 * H;
            const float* xi = s_in + half * 128;
            float a0 = 0.f, a1 = 0.f, a2 = 0.f, a3 = 0.f;
            float a4 = 0.f, a5 = 0.f, a6 = 0.f, a7 = 0.f;
#pragma unroll 16
            for (int k = 0; k < 128; k += 8) {
                a0 = fmaf(xi[k],     __ldg(&w[(k)     * H + col]), a0);
                a1 = fmaf(xi[k + 1], __ldg(&w[(k + 1) * H + col]), a1);
                a2 = fmaf(xi[k + 2], __ldg(&w[(k + 2) * H + col]), a2);
                a3 = fmaf(xi[k + 3], __ldg(&w[(k + 3) * H + col]), a3);
                a4 = fmaf(xi[k + 4], __ldg(&w[(k + 4) * H + col]), a4);
                a5 = fmaf(xi[k + 5], __ldg(&w[(k + 5) * H + col]), a5);
                a6 = fmaf(xi[k + 6], __ldg(&w[(k + 6) * H + col]), a6);
                a7 = fmaf(xi[k + 7], __ldg(&w[(k + 7) * H + col]), a7);
            }
            s_p[half * 128 + col] = (((a0 + a1) + (a2 + a3)) + ((a4 + a5) + (a6 + a7)));
        }
        __syncthreads();
        if (tid < 128) s_h1[tid] = silu_p(bn1[tid] + s_p[tid] + s_p[128 + tid]);
        __syncthreads();
        if (tid < 256) {
            int col = tid & 127, half = tid >> 7;
            const float* hi = s_h1 + half * 64;
            const float* w  = Wn2 + half * 64 * H;
            float a0 = 0.f, a1 = 0.f, a2 = 0.f, a3 = 0.f;
            float a4 = 0.f, a5 = 0.f, a6 = 0.f, a7 = 0.f;
#pragma unroll 8
            for (int k = 0; k < 64; k += 8) {
                a0 = fmaf(hi[k],     __ldg(&w[(k)     * H + col]), a0);
                a1 = fmaf(hi[k + 1], __ldg(&w[(k + 1) * H + col]), a1);
                a2 = fmaf(hi[k + 2], __ldg(&w[(k + 2) * H + col]), a2);
                a3 = fmaf(hi[k + 3], __ldg(&w[(k + 3) * H + col]), a3);
                a4 = fmaf(hi[k + 4], __ldg(&w[(k + 4) * H + col]), a4);
                a5 = fmaf(hi[k + 5], __ldg(&w[(k + 5) * H + col]), a5);
                a6 = fmaf(hi[k + 6], __ldg(&w[(k + 6) * H + col]), a6);
                a7 = fmaf(hi[k + 7], __ldg(&w[(k + 7) * H + col]), a7);
            }
            s_p[half * 128 + col] = (((a0 + a1) + (a2 + a3)) + ((a4 + a5) + (a6 + a7)));
        }
        __syncthreads();
        if (tid < 128)
            out[(b * NF + tid) * C + c] =
                vnf[(b * NF + tid) * C + c] + bn2[tid] + s_p[tid] + s_p[128 + tid];
        __syncthreads();
    }
    // coord output
    for (int i = bid * THREADS + tid; i < B * 9; i += NBLK * THREADS) {
        int b = i / 9;
        float cnt = fmaxf(g_cnt[b], 1.0f);
        out[B * NF * C + i] = vcoord[i] + g_aggT[i] / cnt;
    }
}

// ---------------------------------------------------------------------------
extern "C" void kernel_launch(void* const* d_in, const int* in_sizes, int n_in,
                              void* d_out, int out_size) {
    const float* node_feat = (const float*)d_in[0];
    const float* coord     = (const float*)d_in[1];
    const float* vnf       = (const float*)d_in[2];
    const float* vcoord    = (const float*)d_in[3];
    const int*   batch     = (const int*)  d_in[4];
    const float* We1 = (const float*)d_in[5];
    const float* be1 = (const float*)d_in[6];
    const float* We2 = (const float*)d_in[7];
    const float* be2 = (const float*)d_in[8];
    const float* Wc1 = (const float*)d_in[9];
    const float* bc1 = (const float*)d_in[10];
    const float* Wc2 = (const float*)d_in[11];
    const float* Wn1 = (const float*)d_in[12];
    const float* bn1 = (const float*)d_in[13];
    const float* Wn2 = (const float*)d_in[14];
    const float* bn2 = (const float*)d_in[15];

    int N = in_sizes[0] / NF;
    int B = in_sizes[2] / (NF * C);

    cudaFuncSetAttribute(egcl_kernel,
                         cudaFuncAttributeMaxDynamicSharedMemorySize, SMEM_TOTAL);

    egcl_kernel<<<NBLK, THREADS, SMEM_TOTAL>>>(
        node_feat, coord, vnf, vcoord, batch,
        We1, be1, We2, be2, Wc1, bc1, Wc2, Wn1, bn1, Wn2, bn2,
        (float*)d_out, N, B);
}

// round 14
// speedup vs baseline: 1.1394x; 1.0979x over previous
#include <cuda_runtime.h>
#include <cuda_bf16.h>
#include <cuda_fp16.h>
#include <cstdint>

// EGCL_A2V — bf16 HMMA + ldmatrix, 192-row tiles, 12 warps as 6 pairs.
// Fast path: M=32 x N=64 warp tiles (B fragments shared across 2 m-frags:
// -33% ldsm traffic), pair-local named barriers, 2 __syncthreads per tile.
// Slow path: R11-proven M=16 body.

#define NF 128
#define H  128
#define C  3
#define B_MAX 256
#define THREADS 384
#define NW 12
#define TILE 192
#define NBLK 148
#define PAD 136
#define WSTRIDE (128*PAD)
#define BSTEP (16 * PAD * 2)

#define SMEM_SW 0
#define SMEM_SA 104448
#define SMEM_F  156672
#define SMEM_TOTAL 193280

// float-region layout
#define F_WR    0
#define F_BE2   128
#define F_BC1   256
#define F_WC2   384
#define F_SRAD  512          // [192][3]
#define F_SDIFF 1088         // [192][9]
#define F_SSM2  2816         // [3][192][2] (slow path uses first 192)
#define F_SWP   3968         // [3][6][128]
#define F_SBID  6272         // int[192]

__device__ float g_V1[B_MAX * C * H];
__device__ float g_aggM[B_MAX * C * H];
__device__ float g_aggT[B_MAX * 9];
__device__ float g_cnt[B_MAX];
__device__ unsigned g_tile;
__device__ __align__(16) __nv_bfloat16 g_Wimg[3 * WSTRIDE];

// ---------------- helpers ----------------
__device__ __forceinline__ float silu_p(float x) { return x / (1.0f + __expf(-x)); }

__device__ __forceinline__ float2 silu2(float f0, float f1) {
    __half2 h  = __floats2half2_rn(f0, f1);
    __half2 hx = __hmul2(h, __float2half2_rn(0.5f));
    uint32_t hu = *reinterpret_cast<uint32_t*>(&hx);
    uint32_t tu;
    asm("tanh.approx.f16x2 %0, %1;" : "=r"(tu) : "r"(hu));
    __half2 t = *reinterpret_cast<__half2*>(&tu);
    __half2 s = __hfma2(hx, t, hx);
    return __half22float2(s);
}
__device__ __forceinline__ uint32_t pack_bf16(float lo, float hi) {
    uint32_t r;
    asm("cvt.rn.bf16x2.f32 %0, %1, %2;" : "=r"(r) : "f"(hi), "f"(lo));
    return r;
}
__device__ __forceinline__ float2 unpack_bf16(uint32_t u) {
    __nv_bfloat162 h = *reinterpret_cast<__nv_bfloat162*>(&u);
    return __bfloat1622float2(h);
}
__device__ __forceinline__ uint32_t smem_u32(const void* p) {
    uint32_t a;
    asm("{ .reg .u64 t; cvta.to.shared.u64 t, %1; cvt.u32.u64 %0, t; }" : "=r"(a) : "l"(p));
    return a;
}
__device__ __forceinline__ void ldsm_x4(uint32_t* r, uint32_t addr) {
    asm volatile("ldmatrix.sync.aligned.m8n8.x4.shared.b16 {%0,%1,%2,%3}, [%4];"
                 : "=r"(r[0]), "=r"(r[1]), "=r"(r[2]), "=r"(r[3]) : "r"(addr));
}
__device__ __forceinline__ void mma16816(float* d,
        uint32_t a0, uint32_t a1, uint32_t a2, uint32_t a3,
        uint32_t b0, uint32_t b1) {
    asm volatile(
        "mma.sync.aligned.m16n8k16.row.col.f32.bf16.bf16.f32 "
        "{%0,%1,%2,%3}, {%4,%5,%6,%7}, {%8,%9}, {%0,%1,%2,%3};"
        : "+f"(d[0]), "+f"(d[1]), "+f"(d[2]), "+f"(d[3])
        : "r"(a0), "r"(a1), "r"(a2), "r"(a3), "r"(b0), "r"(b1));
}
// pair-local named barrier (2 warps = 64 threads), ids 1..6
__device__ __forceinline__ void bar_pair(int id) {
    asm volatile("bar.sync %0, 64;" :: "r"(id) : "memory");
}

// M=16 GEMM (slow path)
__device__ __forceinline__ void gemm128(uint32_t aAddr, uint32_t bAddr, float* acc) {
#pragma unroll 2
    for (int ks = 0; ks < 8; ks++) {
        uint32_t A[4];
        ldsm_x4(A, aAddr + ks * 32);
#pragma unroll
        for (int ntp = 0; ntp < 8; ntp++) {
            uint32_t Bf[4];
            ldsm_x4(Bf, bAddr + ntp * BSTEP + ks * 32);
            mma16816(acc + ntp * 8,     A[0], A[1], A[2], A[3], Bf[0], Bf[1]);
            mma16816(acc + ntp * 8 + 4, A[0], A[1], A[2], A[3], Bf[2], Bf[3]);
        }
    }
}
// M=32 x N=64 GEMM (fast path): B fragment reused by both m-frags.
// acc[mf*32 + nt*4 + j]: row = mb*32 + mf*16 + (lane>>2) (+8 for j>=2),
// col = nb*64 + nt*8 + (lane&3)*2 (+1 for odd j).
__device__ __forceinline__ void gemm32x64(uint32_t aAddr, uint32_t bAddr, float* acc) {
#pragma unroll 2
    for (int ks = 0; ks < 8; ks++) {
        uint32_t A0[4], A1[4];
        ldsm_x4(A0, aAddr + ks * 32);
        ldsm_x4(A1, aAddr + 16 * PAD * 2 + ks * 32);
#pragma unroll
        for (int ntp = 0; ntp < 4; ntp++) {
            uint32_t Bf[4];
            ldsm_x4(Bf, bAddr + ntp * BSTEP + ks * 32);
            mma16816(acc + (ntp * 2) * 4,          A0[0], A0[1], A0[2], A0[3], Bf[0], Bf[1]);
            mma16816(acc + (ntp * 2 + 1) * 4,      A0[0], A0[1], A0[2], A0[3], Bf[2], Bf[3]);
            mma16816(acc + 32 + (ntp * 2) * 4,     A1[0], A1[1], A1[2], A1[3], Bf[0], Bf[1]);
            mma16816(acc + 32 + (ntp * 2 + 1) * 4, A1[0], A1[1], A1[2], A1[3], Bf[2], Bf[3]);
        }
    }
}

// ---------------------------------------------------------------------------
__global__ void prep_img(const float* __restrict__ We1,
                         const float* __restrict__ We2,
                         const float* __restrict__ Wc1,
                         __nv_bfloat16* __restrict__ gW) {
    int w = blockIdx.x >> 7, k = blockIdx.x & 127, n = threadIdx.x;
    const float* W = (w == 0) ? We1 : (w == 1) ? We2 : Wc1;
    gW[w * WSTRIDE + n * PAD + k] = __float2bfloat16(W[k * H + n]);
}

// ---------------------------------------------------------------------------
__global__ void prep_V1(const float* __restrict__ vnf,
                        const float* __restrict__ We1,
                        const float* __restrict__ be1) {
    __shared__ float sv[NF];
    int h = threadIdx.x, bc = blockIdx.x;
    int b = bc / C, c = bc % C;
    sv[h] = vnf[(b * NF + h) * C + c];
    __syncthreads();
    const float* w = We1 + NF * H;
    float a0 = 0.f, a1 = 0.f, a2 = 0.f, a3 = 0.f;
    float a4 = 0.f, a5 = 0.f, a6 = 0.f, a7 = 0.f;
#pragma unroll 4
    for (int f = 0; f < NF; f += 8) {
        a0 = fmaf(sv[f],     __ldg(&w[(f)     * H + h]), a0);
        a1 = fmaf(sv[f + 1], __ldg(&w[(f + 1) * H + h]), a1);
        a2 = fmaf(sv[f + 2], __ldg(&w[(f + 2) * H + h]), a2);
        a3 = fmaf(sv[f + 3], __ldg(&w[(f + 3) * H + h]), a3);
        a4 = fmaf(sv[f + 4], __ldg(&w[(f + 4) * H + h]), a4);
        a5 = fmaf(sv[f + 5], __ldg(&w[(f + 5) * H + h]), a5);
        a6 = fmaf(sv[f + 6], __ldg(&w[(f + 6) * H + h]), a6);
        a7 = fmaf(sv[f + 7], __ldg(&w[(f + 7) * H + h]), a7);
    }
    g_V1[bc * H + h] = be1[h] + (((a0 + a1) + (a2 + a3)) + ((a4 + a5) + (a6 + a7)));
    g_aggM[bc * H + h] = 0.0f;
    if (bc == 0) {
        for (int i = h; i < B_MAX * 9; i += blockDim.x) g_aggT[i] = 0.0f;
        for (int i = h; i < B_MAX; i += blockDim.x) g_cnt[i] = 0.0f;
        if (h == 0) g_tile = 0u;
    }
}

// ---------------------------------------------------------------------------
__global__ void __launch_bounds__(THREADS, 1)
main_kernel(const float* __restrict__ node_feat,
            const float* __restrict__ coord,
            const float* __restrict__ vcoord,
            const int*   __restrict__ batch,
            const float* __restrict__ We1,
            const float* __restrict__ be2,
            const float* __restrict__ bc1,
            const float* __restrict__ Wc2,
            int N) {
    extern __shared__ __align__(16) char smem[];
    __nv_bfloat16* sW = (__nv_bfloat16*)(smem + SMEM_SW);
    __nv_bfloat16* sA = (__nv_bfloat16*)(smem + SMEM_SA);
    float* sf = (float*)(smem + SMEM_F);
    float* swr   = sf + F_WR;
    float* sbe2  = sf + F_BE2;
    float* sbc1  = sf + F_BC1;
    float* swc2  = sf + F_WC2;
    float* srad  = sf + F_SRAD;
    float* sdiff = sf + F_SDIFF;
    float* ssm2  = sf + F_SSM2;
    float* swp   = sf + F_SWP;
    int*   sbid  = (int*)(sf + F_SBID);
    __shared__ int s_tile;

    const int tid = threadIdx.x, lane = tid & 31, warp = tid >> 5;
    const int mb = warp >> 1, nb = warp & 1;

    {   // weights -> smem
        const uint4* src = (const uint4*)g_Wimg;
        uint4* dst = (uint4*)sW;
        for (int i = tid; i < 3 * WSTRIDE * 2 / 16; i += THREADS) dst[i] = src[i];
    }
    if (tid < 128) {
        swr[tid]  = We1[256 * H + tid];
        sbe2[tid] = be2[tid];
        sbc1[tid] = bc1[tid];
        swc2[tid] = Wc2[tid];
    }
    __syncthreads();

    const uint32_t sA_u = smem_u32(sA);
    const uint32_t sW_u = smem_u32(sW);
    const uint32_t bRel =
        (((((lane >> 4) & 1) * 8 + (lane & 7)) * PAD + ((lane >> 3) & 1) * 8) << 1);
    // slow-path (M=16) addressing
    const uint32_t aAddrS = sA_u +
        (((warp * 16 + (lane & 15)) * PAD + (lane >> 4) * 8) << 1);
    const uint32_t bAddrS0 = sW_u + bRel;
    const uint32_t bAddrS1 = bAddrS0 + WSTRIDE * 2;
    const uint32_t bAddrS2 = bAddrS1 + WSTRIDE * 2;
    const int r0s = warp * 16 + (lane >> 2), r1s = r0s + 8;
    // fast-path (M=32 x N=64) addressing
    const uint32_t aAddrF = sA_u +
        (((mb * 32 + (lane & 15)) * PAD + (lane >> 4) * 8) << 1);
    const uint32_t bAddrF0 = sW_u + bRel + (uint32_t)(nb * 64 * PAD * 2);
    const uint32_t bAddrF1 = bAddrF0 + WSTRIDE * 2;
    const uint32_t bAddrF2 = bAddrF1 + WSTRIDE * 2;
    const int rF = mb * 32 + (lane >> 2);      // + mf*16, +8

    const int ntiles = (N + TILE - 1) / TILE;
    for (;;) {
        if (tid == 0) s_tile = (int)atomicAdd(&g_tile, 1u);
        __syncthreads();                       // B1 (fences prev-tile agg too)
        const int t = s_tile;
        if (t >= ntiles) break;
        const int base = t * TILE;

        const bool tileFull = (base + TILE <= N);
        const int bFirst = __ldg(&batch[base]);
        const int bLast  = __ldg(&batch[min(base + TILE - 1, N - 1)]);
        const bool fast  = tileFull && (bFirst == bLast) && bFirst >= 0;
        const int b0t = bFirst < 0 ? 0 : bFirst;

        if (fast) {
            // ============ FAST PATH: pair-tiled M=32 x N=64 =================
            {   // own 16 rows: mb*32 + nb*16 + (lane>>1)
                int r = mb * 32 + nb * 16 + (lane >> 1), cb = (lane & 1) * 64;
                int n = base + r;
                const float4* nf = (const float4*)(node_feat + (size_t)n * NF + cb);
                __nv_bfloat16* dst = sA + r * PAD + cb;
#pragma unroll
                for (int q = 0; q < 16; q++) {
                    float4 v = __ldg(&nf[q]);
                    *(uint32_t*)(dst + q * 4)     = pack_bf16(v.x, v.y);
                    *(uint32_t*)(dst + q * 4 + 2) = pack_bf16(v.z, v.w);
                }
                if (lane < 16) {   // geometry for row mb*32 + nb*16 + lane
                    int m = mb * 32 + nb * 16 + lane, nn = base + m;
                    float cx = coord[nn * 3 + 0], cy = coord[nn * 3 + 1], cz = coord[nn * 3 + 2];
#pragma unroll
                    for (int cc = 0; cc < C; cc++) {
                        float dx = __ldg(&vcoord[(b0t * 3 + 0) * C + cc]) - cx;
                        float dy = __ldg(&vcoord[(b0t * 3 + 1) * C + cc]) - cy;
                        float dz = __ldg(&vcoord[(b0t * 3 + 2) * C + cc]) - cz;
                        sdiff[m * 9 + cc * 3 + 0] = dx;
                        sdiff[m * 9 + cc * 3 + 1] = dy;
                        sdiff[m * 9 + cc * 3 + 2] = dz;
                        srad[m * 3 + cc] = sqrtf(dx * dx + dy * dy + dz * dz);
                    }
                }
            }
            if (tid == 0) atomicAdd(&g_cnt[b0t], (float)TILE);
            bar_pair(mb + 1);                  // A rows + geometry ready

            // GEMM1 -> xp (packed bf16, acc layout)
            uint32_t xp[32];
            {
                float x1[64];
#pragma unroll
                for (int i = 0; i < 64; i++) x1[i] = 0.f;
                gemm32x64(aAddrF, bAddrF0, x1);
#pragma unroll
                for (int i = 0; i < 32; i++)
                    xp[i] = pack_bf16(x1[i * 2], x1[i * 2 + 1]);
            }
            bar_pair(mb + 1);                  // pair done reading sA(nf)

#pragma unroll 1
            for (int c = 0; c < C; c++) {
                const float* v1p = g_V1 + (b0t * C + c) * H;
                float radv[4];
#pragma unroll
                for (int mf = 0; mf < 2; mf++) {
                    radv[mf * 2 + 0] = srad[(rF + mf * 16) * 3 + c];
                    radv[mf * 2 + 1] = srad[(rF + mf * 16 + 8) * 3 + c];
                }

                // EpA: m1 -> sA (own 32 rows x 64 cols)
#pragma unroll
                for (int nt = 0; nt < 8; nt++) {
                    int c0 = nb * 64 + nt * 8 + (lane & 3) * 2;
                    float2 vv = __ldg((const float2*)(v1p + c0));
                    float w0 = swr[c0], w1 = swr[c0 + 1];
#pragma unroll
                    for (int mf = 0; mf < 2; mf++) {
                        int ib = mf * 16 + nt * 2;
                        float2 xv0 = unpack_bf16(xp[ib]);
                        float2 xv1 = unpack_bf16(xp[ib + 1]);
                        float2 u0 = silu2(xv0.x + vv.x + radv[mf * 2] * w0,
                                          xv0.y + vv.y + radv[mf * 2] * w1);
                        float2 u1 = silu2(xv1.x + vv.x + radv[mf * 2 + 1] * w0,
                                          xv1.y + vv.y + radv[mf * 2 + 1] * w1);
                        int rr = rF + mf * 16;
                        *(uint32_t*)(sA + rr * PAD + c0)       = pack_bf16(u0.x, u0.y);
                        *(uint32_t*)(sA + (rr + 8) * PAD + c0) = pack_bf16(u1.x, u1.y);
                    }
                }
                bar_pair(mb + 1);

                // GEMM2
                float acc[64];
#pragma unroll
                for (int i = 0; i < 64; i++) acc[i] = 0.f;
                gemm32x64(aAddrF, bAddrF1, acc);
                bar_pair(mb + 1);

                // EpB: m2 -> sA + per-pair column sums -> swp[c][mb]
#pragma unroll
                for (int nt = 0; nt < 8; nt++) {
                    int c0 = nb * 64 + nt * 8 + (lane & 3) * 2;
                    float v0 = 0.f, v1 = 0.f;
#pragma unroll
                    for (int mf = 0; mf < 2; mf++) {
                        const float* a = acc + mf * 32 + nt * 4;
                        float2 u0 = silu2(a[0] + sbe2[c0], a[1] + sbe2[c0 + 1]);
                        float2 u1 = silu2(a[2] + sbe2[c0], a[3] + sbe2[c0 + 1]);
                        int rr = rF + mf * 16;
                        *(uint32_t*)(sA + rr * PAD + c0)       = pack_bf16(u0.x, u0.y);
                        *(uint32_t*)(sA + (rr + 8) * PAD + c0) = pack_bf16(u1.x, u1.y);
                        v0 += u0.x + u1.x;
                        v1 += u0.y + u1.y;
                    }
                    v0 += __shfl_xor_sync(0xffffffffu, v0, 4);
                    v0 += __shfl_xor_sync(0xffffffffu, v0, 8);
                    v0 += __shfl_xor_sync(0xffffffffu, v0, 16);
                    v1 += __shfl_xor_sync(0xffffffffu, v1, 4);
                    v1 += __shfl_xor_sync(0xffffffffu, v1, 8);
                    v1 += __shfl_xor_sync(0xffffffffu, v1, 16);
                    if (lane < 4) {
                        swp[(c * 6 + mb) * 128 + c0]     = v0;
                        swp[(c * 6 + mb) * 128 + c0 + 1] = v1;
                    }
                }
                bar_pair(mb + 1);

                // GEMM3
#pragma unroll
                for (int i = 0; i < 64; i++) acc[i] = 0.f;
                gemm32x64(aAddrF, bAddrF2, acc);

                // EpC: partial row scalars over own 64 cols
                {
                    float s00 = 0.f, s01 = 0.f, s10 = 0.f, s11 = 0.f;
#pragma unroll
                    for (int nt = 0; nt < 8; nt++) {
                        int c0 = nb * 64 + nt * 8 + (lane & 3) * 2;
                        float w0 = swc2[c0], w1 = swc2[c0 + 1];
                        {
                            const float* a = acc + nt * 4;
                            float2 u0 = silu2(a[0] + sbc1[c0], a[1] + sbc1[c0 + 1]);
                            float2 u1 = silu2(a[2] + sbc1[c0], a[3] + sbc1[c0 + 1]);
                            s00 += u0.x * w0 + u0.y * w1;
                            s01 += u1.x * w0 + u1.y * w1;
                        }
                        {
                            const float* a = acc + 32 + nt * 4;
                            float2 u0 = silu2(a[0] + sbc1[c0], a[1] + sbc1[c0 + 1]);
                            float2 u1 = silu2(a[2] + sbc1[c0], a[3] + sbc1[c0 + 1]);
                            s10 += u0.x * w0 + u0.y * w1;
                            s11 += u1.x * w0 + u1.y * w1;
                        }
                    }
                    s00 += __shfl_xor_sync(0xffffffffu, s00, 1);
                    s00 += __shfl_xor_sync(0xffffffffu, s00, 2);
                    s01 += __shfl_xor_sync(0xffffffffu, s01, 1);
                    s01 += __shfl_xor_sync(0xffffffffu, s01, 2);
                    s10 += __shfl_xor_sync(0xffffffffu, s10, 1);
                    s10 += __shfl_xor_sync(0xffffffffu, s10, 2);
                    s11 += __shfl_xor_sync(0xffffffffu, s11, 1);
                    s11 += __shfl_xor_sync(0xffffffffu, s11, 2);
                    if ((lane & 3) == 0) {
                        ssm2[c * 384 + (rF)      * 2 + nb] = s00;
                        ssm2[c * 384 + (rF + 8)  * 2 + nb] = s01;
                        ssm2[c * 384 + (rF + 16) * 2 + nb] = s10;
                        ssm2[c * 384 + (rF + 24) * 2 + nb] = s11;
                    }
                }
                bar_pair(mb + 1);   // partner GEMM3 done before next EpA write
            }

            __syncthreads();                   // B2: swp/ssm2/sdiff visible

            // aggM: 128 cols x 3 channels (6 pair partials)
            if (tid < 128) {
#pragma unroll
                for (int c = 0; c < C; c++) {
                    float s = 0.f;
#pragma unroll
                    for (int w = 0; w < 6; w++) s += swp[(c * 6 + w) * 128 + tid];
                    atomicAdd(&g_aggM[(b0t * C + c) * H + tid], s);
                }
            }
            // aggT: 9 (c,d) pairs by warps 0..8
            if (warp < 9) {
                int c = warp / 3, d = warp % 3;
                float v = 0.f;
#pragma unroll
                for (int q = 0; q < TILE / 32; q++) {
                    int r = lane + q * 32;
                    float sv = ssm2[c * 384 + r * 2] + ssm2[c * 384 + r * 2 + 1];
                    v += sdiff[r * 9 + c * 3 + d] * sv;
                }
                v += __shfl_xor_sync(0xffffffffu, v, 16);
                v += __shfl_xor_sync(0xffffffffu, v, 8);
                v += __shfl_xor_sync(0xffffffffu, v, 4);
                v += __shfl_xor_sync(0xffffffffu, v, 2);
                v += __shfl_xor_sync(0xffffffffu, v, 1);
                if (lane == 0) atomicAdd(&g_aggT[b0t * 9 + d * 3 + c], v);
            }
            continue;   // loop-top B1 fences agg reads
        }

        // ================= SLOW PATH (R11 body, M=16) =======================
        if (tid < TILE) {
            int m = tid, n = base + m;
            bool valid = n < N;
            int nc = valid ? n : N - 1;
            int b = valid ? batch[n] : -1;
            sbid[m] = b;
            int bb = b < 0 ? 0 : b;
            float cx = coord[nc * 3 + 0], cy = coord[nc * 3 + 1], cz = coord[nc * 3 + 2];
#pragma unroll
            for (int cc = 0; cc < C; cc++) {
                float dx = __ldg(&vcoord[(bb * 3 + 0) * C + cc]) - cx;
                float dy = __ldg(&vcoord[(bb * 3 + 1) * C + cc]) - cy;
                float dz = __ldg(&vcoord[(bb * 3 + 2) * C + cc]) - cz;
                sdiff[m * 9 + cc * 3 + 0] = dx;
                sdiff[m * 9 + cc * 3 + 1] = dy;
                sdiff[m * 9 + cc * 3 + 2] = dz;
                srad[m * 3 + cc] = sqrtf(dx * dx + dy * dy + dz * dz);
            }
        }
        {
            int r = tid >> 1, cb = (tid & 1) * 64;
            int n = base + r;
            int nc = n < N ? n : N - 1;
            const float4* nf = (const float4*)(node_feat + (size_t)nc * NF + cb);
            __nv_bfloat16* dst = sA + r * PAD + cb;
#pragma unroll
            for (int q = 0; q < 16; q++) {
                float4 v = __ldg(&nf[q]);
                *(uint32_t*)(dst + q * 4)     = pack_bf16(v.x, v.y);
                *(uint32_t*)(dst + q * 4 + 2) = pack_bf16(v.z, v.w);
            }
        }
        __syncthreads();

        if (tid == 0) {
            int cb = sbid[0]; float cl = 0.f;
            for (int r = 0; r < TILE; r++) {
                int b2 = sbid[r];
                if (b2 != cb) { if (cb >= 0) atomicAdd(&g_cnt[cb], cl); cl = 0.f; cb = b2; }
                if (b2 >= 0) cl += 1.f;
            }
            if (cb >= 0) atomicAdd(&g_cnt[cb], cl);
        }

        int bb0 = sbid[r0s]; bb0 = bb0 < 0 ? 0 : bb0;
        int bb1 = sbid[r1s]; bb1 = bb1 < 0 ? 0 : bb1;

        uint32_t xp[32];
        {
            float x1[64];
#pragma unroll
            for (int i = 0; i < 64; i++) x1[i] = 0.f;
            gemm128(aAddrS, bAddrS0, x1);
#pragma unroll
            for (int i = 0; i < 32; i++)
                xp[i] = pack_bf16(x1[i * 2], x1[i * 2 + 1]);
        }
        __syncthreads();

#pragma unroll 1
        for (int c = 0; c < C; c++) {
            float rad0 = srad[r0s * 3 + c], rad1 = srad[r1s * 3 + c];
            const float* v0p = g_V1 + (bb0 * C + c) * H;
            const float* v1p = g_V1 + (bb1 * C + c) * H;
#pragma unroll
            for (int nt = 0; nt < 16; nt++) {
                int c0 = nt * 8 + (lane & 3) * 2;
                float2 xv0 = unpack_bf16(xp[nt * 2 + 0]);
                float2 xv1 = unpack_bf16(xp[nt * 2 + 1]);
                float w0 = swr[c0], w1 = swr[c0 + 1];
                float2 u0 = silu2(xv0.x + __ldg(&v0p[c0])     + rad0 * w0,
                                  xv0.y + __ldg(&v0p[c0 + 1]) + rad0 * w1);
                float2 u1 = silu2(xv1.x + __ldg(&v1p[c0])     + rad1 * w0,
                                  xv1.y + __ldg(&v1p[c0 + 1]) + rad1 * w1);
                *(uint32_t*)(sA + r0s * PAD + c0) = pack_bf16(u0.x, u0.y);
                *(uint32_t*)(sA + r1s * PAD + c0) = pack_bf16(u1.x, u1.y);
            }
            __syncthreads();

            float acc[64];
#pragma unroll
            for (int i = 0; i < 64; i++) acc[i] = 0.f;
            gemm128(aAddrS, bAddrS1, acc);
            __syncthreads();

#pragma unroll
            for (int nt = 0; nt < 16; nt++) {
                int c0 = nt * 8 + (lane & 3) * 2;
                float2 u0 = silu2(acc[nt * 4 + 0] + sbe2[c0], acc[nt * 4 + 1] + sbe2[c0 + 1]);
                float2 u1 = silu2(acc[nt * 4 + 2] + sbe2[c0], acc[nt * 4 + 3] + sbe2[c0 + 1]);
                *(uint32_t*)(sA + r0s * PAD + c0) = pack_bf16(u0.x, u0.y);
                *(uint32_t*)(sA + r1s * PAD + c0) = pack_bf16(u1.x, u1.y);
            }
            __syncthreads();

#pragma unroll
            for (int i = 0; i < 64; i++) acc[i] = 0.f;
            gemm128(aAddrS, bAddrS2, acc);

            {
                float s0 = 0.f, s1 = 0.f;
#pragma unroll
                for (int nt = 0; nt < 16; nt++) {
                    int c0 = nt * 8 + (lane & 3) * 2;
                    float2 u0 = silu2(acc[nt * 4 + 0] + sbc1[c0], acc[nt * 4 + 1] + sbc1[c0 + 1]);
                    float2 u1 = silu2(acc[nt * 4 + 2] + sbc1[c0], acc[nt * 4 + 3] + sbc1[c0 + 1]);
                    s0 += u0.x * swc2[c0] + u0.y * swc2[c0 + 1];
                    s1 += u1.x * swc2[c0] + u1.y * swc2[c0 + 1];
                }
                s0 += __shfl_xor_sync(0xffffffffu, s0, 1);
                s0 += __shfl_xor_sync(0xffffffffu, s0, 2);
                s1 += __shfl_xor_sync(0xffffffffu, s1, 1);
                s1 += __shfl_xor_sync(0xffffffffu, s1, 2);
                if ((lane & 3) == 0) { ssm2[r0s] = s0; ssm2[r1s] = s1; }
            }
            __syncthreads();

            if (tid < 128) {
                int col = tid; float a = 0.f; int cb = sbid[0];
                for (int r = 0; r < TILE; r++) {
                    int b2 = sbid[r];
                    if (b2 != cb) {
                        if (cb >= 0) atomicAdd(&g_aggM[(cb * C + c) * H + col], a);
                        a = 0.f; cb = b2;
                    }
                    if (b2 >= 0) a += __bfloat162float(sA[r * PAD + col]);
                }
                if (cb >= 0) atomicAdd(&g_aggM[(cb * C + c) * H + col], a);
            }
            if (tid >= 128 && tid < 131) {
                int d = tid - 128; float a = 0.f; int cb = sbid[0];
                for (int r = 0; r < TILE; r++) {
                    int b2 = sbid[r];
                    if (b2 != cb) {
                        if (cb >= 0) atomicAdd(&g_aggT[cb * 9 + d * 3 + c], a);
                        a = 0.f; cb = b2;
                    }
                    if (b2 >= 0) a += sdiff[r * 9 + c * 3 + d] * ssm2[r];
                }
                if (cb >= 0) atomicAdd(&g_aggT[cb * 9 + d * 3 + c], a);
            }
            __syncthreads();
        }
    }
}

// ---------------------------------------------------------------------------
__global__ void final_kernel(const float* __restrict__ vnf,
                             const float* __restrict__ vcoord,
                             const float* __restrict__ Wn1, const float* __restrict__ bn1,
                             const float* __restrict__ Wn2, const float* __restrict__ bn2,
                             float* __restrict__ out, int B) {
    __shared__ float s_in[2 * H];
    __shared__ float s_h1[H];
    __shared__ float s_p[2 * H];
    int tid = threadIdx.x;
    int b = blockIdx.x / C, c = blockIdx.x % C;

    float cnt = fmaxf(g_cnt[b], 1.0f);
    if (tid < 128) {
        s_in[tid]       = vnf[(b * NF + tid) * C + c];
        s_in[128 + tid] = g_aggM[(b * C + c) * H + tid] / cnt;
    }
    __syncthreads();
    {
        int col = tid & 127, half = tid >> 7;
        const float* w  = Wn1 + half * 128 * H;
        const float* xi = s_in + half * 128;
        float a0 = 0.f, a1 = 0.f, a2 = 0.f, a3 = 0.f;
        float a4 = 0.f, a5 = 0.f, a6 = 0.f, a7 = 0.f;
#pragma unroll 16
        for (int k = 0; k < 128; k += 8) {
            a0 = fmaf(xi[k],     __ldg(&w[(k)     * H + col]), a0);
            a1 = fmaf(xi[k + 1], __ldg(&w[(k + 1) * H + col]), a1);
            a2 = fmaf(xi[k + 2], __ldg(&w[(k + 2) * H + col]), a2);
            a3 = fmaf(xi[k + 3], __ldg(&w[(k + 3) * H + col]), a3);
            a4 = fmaf(xi[k + 4], __ldg(&w[(k + 4) * H + col]), a4);
            a5 = fmaf(xi[k + 5], __ldg(&w[(k + 5) * H + col]), a5);
            a6 = fmaf(xi[k + 6], __ldg(&w[(k + 6) * H + col]), a6);
            a7 = fmaf(xi[k + 7], __ldg(&w[(k + 7) * H + col]), a7);
        }
        s_p[half * 128 + col] = (((a0 + a1) + (a2 + a3)) + ((a4 + a5) + (a6 + a7)));
    }
    __syncthreads();
    if (tid < 128) s_h1[tid] = silu_p(bn1[tid] + s_p[tid] + s_p[128 + tid]);
    __syncthreads();
    {
        int col = tid & 127, half = tid >> 7;
        const float* hi = s_h1 + half * 64;
        const float* w  = Wn2 + half * 64 * H;
        float a0 = 0.f, a1 = 0.f, a2 = 0.f, a3 = 0.f;
        float a4 = 0.f, a5 = 0.f, a6 = 0.f, a7 = 0.f;
#pragma unroll 8
        for (int k = 0; k < 64; k += 8) {
            a0 = fmaf(hi[k],     __ldg(&w[(k)     * H + col]), a0);
            a1 = fmaf(hi[k + 1], __ldg(&w[(k + 1) * H + col]), a1);
            a2 = fmaf(hi[k + 2], __ldg(&w[(k + 2) * H + col]), a2);
            a3 = fmaf(hi[k + 3], __ldg(&w[(k + 3) * H + col]), a3);
            a4 = fmaf(hi[k + 4], __ldg(&w[(k + 4) * H + col]), a4);
            a5 = fmaf(hi[k + 5], __ldg(&w[(k + 5) * H + col]), a5);
            a6 = fmaf(hi[k + 6], __ldg(&w[(k + 6) * H + col]), a6);
            a7 = fmaf(hi[k + 7], __ldg(&w[(k + 7) * H + col]), a7);
        }
        s_p[half * 128 + col] = (((a0 + a1) + (a2 + a3)) + ((a4 + a5) + (a6 + a7)));
    }
    __syncthreads();
    if (tid < 128)
        out[(b * NF + tid) * C + c] =
            vnf[(b * NF + tid) * C + c] + bn2[tid] + s_p[tid] + s_p[128 + tid];

    if (c == 0 && tid >= 128 && tid < 137) {
        int t = tid - 128;
        int d = t / 3, cc = t % 3;
        int idx = (b * 3 + d) * C + cc;
        out[B * NF * C + idx] = vcoord[idx] + g_aggT[idx] / cnt;
    }
}

// ---------------------------------------------------------------------------
extern "C" void kernel_launch(void* const* d_in, const int* in_sizes, int n_in,
                              void* d_out, int out_size) {
    const float* node_feat = (const float*)d_in[0];
    const float* coord     = (const float*)d_in[1];
    const float* vnf       = (const float*)d_in[2];
    const float* vcoord    = (const float*)d_in[3];
    const int*   batch     = (const int*)  d_in[4];
    const float* We1 = (const float*)d_in[5];
    const float* be1 = (const float*)d_in[6];
    const float* We2 = (const float*)d_in[7];
    const float* be2 = (const float*)d_in[8];
    const float* Wc1 = (const float*)d_in[9];
    const float* bc1 = (const float*)d_in[10];
    const float* Wc2 = (const float*)d_in[11];
    const float* Wn1 = (const float*)d_in[12];
    const float* bn1 = (const float*)d_in[13];
    const float* Wn2 = (const float*)d_in[14];
    const float* bn2 = (const float*)d_in[15];

    int N = in_sizes[0] / NF;
    int B = in_sizes[2] / (NF * C);

    cudaFuncSetAttribute(main_kernel,
                         cudaFuncAttributeMaxDynamicSharedMemorySize, SMEM_TOTAL);

    __nv_bfloat16* gW = nullptr;
    cudaGetSymbolAddress((void**)&gW, g_Wimg);

    prep_img<<<3 * 128, 128>>>(We1, We2, Wc1, gW);
    prep_V1<<<B * C, 128>>>(vnf, We1, be1);
    main_kernel<<<NBLK, THREADS, SMEM_TOTAL>>>(node_feat, coord, vcoord, batch,
                                               We1, be2, bc1, Wc2, N);
    final_kernel<<<B * C, 256>>>(vnf, vcoord, Wn1, bn1, Wn2, bn2,
                                 (float*)d_out, B);
}